// round 2
// baseline (speedup 1.0000x reference)
#include <cuda_runtime.h>
#include <math.h>

#define NN 12800
#define GG 128
#define EB 51200
#define EC 204800

typedef unsigned long long u64;

__device__ __forceinline__ u64 ffma2(u64 a, u64 b, u64 c) {
    u64 d;
    asm("fma.rn.f32x2 %0, %1, %2, %3;" : "=l"(d) : "l"(a), "l"(b), "l"(c));
    return d;
}
__device__ __forceinline__ float2 unpk(u64 v) {
    float2 r;
    asm("mov.b64 {%0, %1}, %2;" : "=f"(r.x), "=f"(r.y) : "l"(v));
    return r;
}

// ---------------- scratch (no allocations allowed) ----------------
__device__ float g_hA[NN*128];
__device__ float g_hB[NN*128];
__device__ float g_ef[EB*128];
__device__ float g_X[NN*512];      // [A1 | A2+b1 | B1 | B2+preb] per node
__device__ float g_C[EB*128];      // ef @ P3 per layer
__device__ float g_agg[NN*1024];   // [bond agg(512) | comp agg(512)]
__device__ float g_t1[NN*128];
__device__ float g_Wx[5*128*512];
__device__ float g_bx[5*512];
__device__ float g_We[5*1152*128];

// ---------------- weight packing ----------------
__global__ void pack_wx_kernel(const float* __restrict__ pcW1, const float* __restrict__ preW,
                               const float* __restrict__ pcB1, const float* __restrict__ preB) {
    int idx = blockIdx.x * 256 + threadIdx.x;
    if (idx < 5*128*512) {
        int l = idx >> 16;
        int rem = idx & 65535;
        int k = rem >> 9;
        int c = rem & 511;
        float v;
        if (c < 128)      v = pcW1[l*32768 + k*128 + c];
        else if (c < 256) v = pcW1[l*32768 + (128+k)*128 + (c-128)];
        else if (c < 384) v = preW[l*49152 + k*128 + (c-256)];
        else              v = preW[l*49152 + (128+k)*128 + (c-384)];
        g_Wx[idx] = v;
    }
    if (idx < 5*512) {
        int l = idx >> 9, c = idx & 511;
        float v = 0.f;
        if (c >= 128 && c < 256) v = pcB1[l*128 + (c-128)];
        else if (c >= 384)       v = preB[l*128 + (c-384)];
        g_bx[idx] = v;
    }
}

__global__ void pack_we_kernel(const float* __restrict__ postW) {
    int idx = blockIdx.x * 256 + threadIdx.x;
    if (idx >= 5*1152*128) return;
    int l = idx / 147456;
    int rem = idx - l*147456;
    int r = rem >> 7, j = rem & 127;
    const float* Wl = postW + (size_t)l*409600;
    float log5  = logf(5.f);
    float log17 = logf(17.f);
    float v;
    if (r < 128) {
        v = Wl[r*128 + j] + ((r == j) ? 1.f : 0.f);   // residual folded in
    } else if (r < 640) {
        int rp = r - 128;
        v = Wl[(128+rp)*128+j] + log5*Wl[(640+rp)*128+j] + Wl[(1152+rp)*128+j]*(1.f/log5);
    } else {
        int rp = r - 640;
        v = Wl[(1664+rp)*128+j] + log17*Wl[(2176+rp)*128+j] + Wl[(2688+rp)*128+j]*(1.f/log17);
    }
    g_We[idx] = v;
}

// ---------------- f32x2 tiled GEMM: out = act(A @ W + bias) ----------------
// A virtually concatenated: cols [0,Ksplit) from A0, rest from A1.
// Tile: TM x 128, 256 threads, each thread RPT rows x 8 cols.
// A stored DUPLICATED in smem so a broadcast-pair is one native LDS;
// B pairs are native adjacent columns -> zero pack MOVs in the inner loop.
template<bool RELU, int TM>
__global__ __launch_bounds__(256) void gemm2_kernel(
    const float* __restrict__ A0, int lda0,
    const float* __restrict__ A1, int lda1, int Ksplit,
    const float* __restrict__ W, int ldw,
    const float* __restrict__ bias,
    float* __restrict__ out, int ldo, int K)
{
    constexpr int RPT = TM / 16;
    __shared__ __align__(16) float As2[16][2*TM];
    __shared__ __align__(16) float Bs[16][128];
    const int t  = threadIdx.x;
    const int m0 = blockIdx.x * TM;
    const int n0 = blockIdx.y * 128;
    const int tr = t >> 4, tc = t & 15;

    int r, ak;
    if (TM == 128) { r = t >> 1; ak = (t & 1) * 8; }
    else           { r = t >> 2; ak = (t & 3) * 4; }

    u64 acc[RPT][4];
#pragma unroll
    for (int i = 0; i < RPT; i++)
#pragma unroll
        for (int p = 0; p < 4; p++) acc[i][p] = 0ull;

    for (int k0 = 0; k0 < K; k0 += 16) {
        {   // A tile (duplicated stores)
            int kg = k0 + ak;
            const float* ap = (kg < Ksplit)
                ? A0 + (size_t)(m0 + r) * lda0 + kg
                : A1 + (size_t)(m0 + r) * lda1 + (kg - Ksplit);
            if (TM == 128) {
                float4 a0 = *(const float4*)ap;
                float4 a1 = *(const float4*)(ap + 4);
                float v[8] = {a0.x,a0.y,a0.z,a0.w,a1.x,a1.y,a1.z,a1.w};
#pragma unroll
                for (int j = 0; j < 8; j++)
                    *(float2*)&As2[ak+j][2*r] = make_float2(v[j], v[j]);
            } else {
                float4 a0 = *(const float4*)ap;
                float v[4] = {a0.x,a0.y,a0.z,a0.w};
#pragma unroll
                for (int j = 0; j < 4; j++)
                    *(float2*)&As2[ak+j][2*r] = make_float2(v[j], v[j]);
            }
        }
#pragma unroll
        for (int i = 0; i < 2; i++) {   // W tile
            int off = t*8 + i*4;
            int kk = off >> 7, j = off & 127;
            *(float4*)&Bs[kk][j] = *(const float4*)&W[(size_t)(k0+kk)*ldw + n0 + j];
        }
        __syncthreads();
#pragma unroll
        for (int kk = 0; kk < 16; kk++) {
            u64 a[RPT], b[4];
#pragma unroll
            for (int q = 0; q < RPT/2; q++) {
                ulonglong2 av = *(const ulonglong2*)&As2[kk][2*RPT*tr + 4*q];
                a[2*q] = av.x; a[2*q+1] = av.y;
            }
            ulonglong2 b0 = *(const ulonglong2*)&Bs[kk][tc*8];
            ulonglong2 b1 = *(const ulonglong2*)&Bs[kk][tc*8 + 4];
            b[0]=b0.x; b[1]=b0.y; b[2]=b1.x; b[3]=b1.y;
#pragma unroll
            for (int i = 0; i < RPT; i++)
#pragma unroll
                for (int p = 0; p < 4; p++)
                    acc[i][p] = ffma2(a[i], b[p], acc[i][p]);
        }
        __syncthreads();
    }
    float bv[8];
    if (bias) {
        float4 x = *(const float4*)&bias[n0 + tc*8];
        float4 y = *(const float4*)&bias[n0 + tc*8 + 4];
        bv[0]=x.x; bv[1]=x.y; bv[2]=x.z; bv[3]=x.w;
        bv[4]=y.x; bv[5]=y.y; bv[6]=y.z; bv[7]=y.w;
    } else {
#pragma unroll
        for (int j = 0; j < 8; j++) bv[j] = 0.f;
    }
#pragma unroll
    for (int i = 0; i < RPT; i++) {
        float o[8];
#pragma unroll
        for (int p = 0; p < 4; p++) {
            float2 v = unpk(acc[i][p]);
            o[2*p]   = v.x + bv[2*p];
            o[2*p+1] = v.y + bv[2*p+1];
        }
        if (RELU) {
#pragma unroll
            for (int j = 0; j < 8; j++) o[j] = fmaxf(o[j], 0.f);
        }
        float* po = &out[(size_t)(m0 + tr*RPT + i)*ldo + n0 + tc*8];
        *(float4*)po     = make_float4(o[0],o[1],o[2],o[3]);
        *(float4*)(po+4) = make_float4(o[4],o[5],o[6],o[7]);
    }
}

// ---------------- fused comp-edge kernel (f32x2) ----------------
// Per 64-edge tile: a = relu(X[src,0:128] + X[dst,128:256]); m = a @ W2 + b2;
// gate = sigmoid(m . seW + seb); ec = m*gate; PNA stats over 16-edge groups.
// Rows pair natively (k-major As); W2 stored duplicated in smem.
__global__ __launch_bounds__(256) void comp_kernel(
    const int* __restrict__ src,
    const float* __restrict__ W2,
    const float* __restrict__ b2,
    const float* __restrict__ seW,
    const float* __restrict__ seB)
{
    __shared__ __align__(16) float As[128][64];    // k-major, 32 KB
    __shared__ __align__(16) float Bs2[16][256];   // duplicated cols, 16 KB
    __shared__ float sRed[8][16];
    const int t  = threadIdx.x;
    const int e0 = blockIdx.x * 64;

    {   // build A tile: gather + add + relu
        int e = t & 63, kq = t >> 6;
        int s = src[e0 + e];
        int node = (e0 >> 4) + (e >> 4);
        const float* x1 = g_X + (size_t)s*512;
        const float* x2 = g_X + (size_t)node*512 + 128;
#pragma unroll
        for (int q = 0; q < 8; q++) {
            int k = kq*32 + q*4;
            float4 a = *(const float4*)(x1 + k);
            float4 b = *(const float4*)(x2 + k);
            As[k+0][e] = fmaxf(a.x+b.x, 0.f);
            As[k+1][e] = fmaxf(a.y+b.y, 0.f);
            As[k+2][e] = fmaxf(a.z+b.z, 0.f);
            As[k+3][e] = fmaxf(a.w+b.w, 0.f);
        }
    }

    const int tc = t & 63, tr = t >> 6;  // tc: col pair, tr: node group (16 rows)
    u64 acc[8][2];
#pragma unroll
    for (int p = 0; p < 8; p++) { acc[p][0] = 0ull; acc[p][1] = 0ull; }

    for (int k0 = 0; k0 < 128; k0 += 16) {
#pragma unroll
        for (int i = 0; i < 2; i++) {    // W2 tile, duplicated
            int off = t*8 + i*4;
            int kk = off >> 7, j = off & 127;
            float4 w = *(const float4*)&W2[(k0+kk)*128 + j];
            *(float2*)&Bs2[kk][2*j+0] = make_float2(w.x, w.x);
            *(float2*)&Bs2[kk][2*j+2] = make_float2(w.y, w.y);
            *(float2*)&Bs2[kk][2*j+4] = make_float2(w.z, w.z);
            *(float2*)&Bs2[kk][2*j+6] = make_float2(w.w, w.w);
        }
        __syncthreads();
#pragma unroll
        for (int kk = 0; kk < 16; kk++) {
            int k = k0 + kk;
            u64 a[8];
#pragma unroll
            for (int q = 0; q < 4; q++) {
                ulonglong2 av = *(const ulonglong2*)&As[k][tr*16 + 4*q];
                a[2*q] = av.x; a[2*q+1] = av.y;
            }
            ulonglong2 bd = *(const ulonglong2*)&Bs2[kk][4*tc];
#pragma unroll
            for (int p = 0; p < 8; p++) {
                acc[p][0] = ffma2(a[p], bd.x, acc[p][0]);
                acc[p][1] = ffma2(a[p], bd.y, acc[p][1]);
            }
        }
        __syncthreads();
    }

    // unpack pairs -> per-row values
    float m[16][2];
#pragma unroll
    for (int p = 0; p < 8; p++) {
        float2 v0 = unpk(acc[p][0]);
        float2 v1 = unpk(acc[p][1]);
        m[2*p][0]   = v0.x; m[2*p+1][0] = v0.y;
        m[2*p][1]   = v1.x; m[2*p+1][1] = v1.y;
    }

    // epilogue: bias, gate (row reduction), PNA stats over 16 rows
    int j0 = tc*2;
    float bb0 = b2[j0], bb1 = b2[j0+1];
    float sw0 = seW[j0], sw1 = seW[j0+1];
    float p[16];
#pragma unroll
    for (int i = 0; i < 16; i++) {
        m[i][0] += bb0; m[i][1] += bb1;
        p[i] = m[i][0]*sw0 + m[i][1]*sw1;
    }
#pragma unroll
    for (int off = 16; off > 0; off >>= 1)
#pragma unroll
        for (int i = 0; i < 16; i++)
            p[i] += __shfl_xor_sync(0xffffffffu, p[i], off);
    if ((t & 31) == 0) {
        int w = t >> 5;
#pragma unroll
        for (int i = 0; i < 16; i++) sRed[w][i] = p[i];
    }
    __syncthreads();
    float sb = seB[0];
    float s0=0.f,s1=0.f,q0=0.f,q1=0.f;
    float mx0=-INFINITY,mx1=-INFINITY,mn0=INFINITY,mn1=INFINITY;
#pragma unroll
    for (int i = 0; i < 16; i++) {
        float sum = sRed[2*tr][i] + sRed[2*tr+1][i] + sb;
        float g = 1.f / (1.f + expf(-sum));
        float e0v = m[i][0]*g, e1v = m[i][1]*g;
        s0 += e0v; q0 += e0v*e0v; mx0 = fmaxf(mx0, e0v); mn0 = fminf(mn0, e0v);
        s1 += e1v; q1 += e1v*e1v; mx1 = fmaxf(mx1, e1v); mn1 = fminf(mn1, e1v);
    }
    int node = (e0 >> 4) + tr;
    float* o = g_agg + (size_t)node*1024 + 512 + j0;
    float m0v = s0*0.0625f, m1v = s1*0.0625f;
    float sd0 = sqrtf(fmaxf(q0*0.0625f - m0v*m0v, 0.f) + 1e-5f);
    float sd1 = sqrtf(fmaxf(q1*0.0625f - m1v*m1v, 0.f) + 1e-5f);
    o[0]   = m0v; o[1]   = m1v;
    o[128] = mx0; o[129] = mx1;
    o[256] = mn0; o[257] = mn1;
    o[384] = sd0; o[385] = sd1;
}

// ---------------- bond-edge PNA (gather-add only, no GEMM) ----------------
__global__ __launch_bounds__(256) void bond_kernel(const int* __restrict__ src) {
    int idx = blockIdx.x*256 + threadIdx.x;   // NN*128 total
    int n = idx >> 7, j = idx & 127;
    float base = g_X[(size_t)n*512 + 384 + j];
    float s=0.f, q=0.f, mx=-INFINITY, mn=INFINITY;
#pragma unroll
    for (int e = 0; e < 4; e++) {
        int ei = n*4 + e;
        int sv = src[ei];
        float v = g_X[(size_t)sv*512 + 256 + j] + base + g_C[(size_t)ei*128 + j];
        s += v; q += v*v; mx = fmaxf(mx, v); mn = fminf(mn, v);
    }
    float mean = s*0.25f;
    float sd = sqrtf(fmaxf(q*0.25f - mean*mean, 0.f) + 1e-5f);
    float* o = g_agg + (size_t)n*1024 + j;
    o[0] = mean; o[128] = mx; o[256] = mn; o[384] = sd;
}

// ---------------- readout: per-graph sum/mean/max + 2-layer MLP ----------------
__global__ __launch_bounds__(128) void readout_kernel(
    const float* __restrict__ h3,
    const float* __restrict__ W1, const float* __restrict__ b1,
    const float* __restrict__ W2, const float* __restrict__ b2,
    float* __restrict__ out)
{
    __shared__ float r[384];
    __shared__ float tb[128];
    int g = blockIdx.x, j = threadIdx.x;
    const float* p = h3 + (size_t)g*100*128 + j;
    float s = 0.f, mx = -INFINITY;
    for (int i = 0; i < 100; i++) {
        float v = p[i*128];
        s += v; mx = fmaxf(mx, v);
    }
    r[j] = s; r[128+j] = s/100.f; r[256+j] = mx;
    __syncthreads();
    float a = b1[j];
    for (int k = 0; k < 384; k++) a += r[k]*W1[k*128 + j];
    tb[j] = fmaxf(a, 0.f);
    __syncthreads();
    if (j < 32) {
        float o = b2[j];
        for (int k = 0; k < 128; k++) o += tb[k]*W2[k*32 + j];
        out[g*32 + j] = o;
    }
}

// ---------------- launcher ----------------
extern "C" void kernel_launch(void* const* d_in, const int* in_sizes, int n_in,
                              void* d_out, int out_size) {
    const float* node_feat = (const float*)d_in[0];
    const float* edge_feat = (const float*)d_in[1];
    const int*   bond_src  = (const int*)d_in[2];
    const int*   comp_src  = (const int*)d_in[4];
    const float* in_W   = (const float*)d_in[7];
    const float* in_b   = (const float*)d_in[8];
    const float* ein_W  = (const float*)d_in[9];
    const float* ein_b  = (const float*)d_in[10];
    const float* pre_W  = (const float*)d_in[11];
    const float* pre_b  = (const float*)d_in[12];
    const float* pc_W1  = (const float*)d_in[13];
    const float* pc_b1  = (const float*)d_in[14];
    const float* pc_W2  = (const float*)d_in[15];
    const float* pc_b2  = (const float*)d_in[16];
    const float* se_W   = (const float*)d_in[17];
    const float* se_b   = (const float*)d_in[18];
    const float* post_W = (const float*)d_in[19];
    const float* post_b = (const float*)d_in[20];
    const float* outn_W1 = (const float*)d_in[21];
    const float* outn_b1 = (const float*)d_in[22];
    const float* outn_W2 = (const float*)d_in[23];
    const float* outn_b2 = (const float*)d_in[24];
    const float* ro_W1 = (const float*)d_in[25];
    const float* ro_b1 = (const float*)d_in[26];
    const float* ro_W2 = (const float*)d_in[27];
    const float* ro_b2 = (const float*)d_in[28];

    float *hA, *hB, *ef, *X, *C, *agg, *t1, *Wx, *bx, *We;
    cudaGetSymbolAddress((void**)&hA, g_hA);
    cudaGetSymbolAddress((void**)&hB, g_hB);
    cudaGetSymbolAddress((void**)&ef, g_ef);
    cudaGetSymbolAddress((void**)&X,  g_X);
    cudaGetSymbolAddress((void**)&C,  g_C);
    cudaGetSymbolAddress((void**)&agg, g_agg);
    cudaGetSymbolAddress((void**)&t1, g_t1);
    cudaGetSymbolAddress((void**)&Wx, g_Wx);
    cudaGetSymbolAddress((void**)&bx, g_bx);
    cudaGetSymbolAddress((void**)&We, g_We);

    pack_wx_kernel<<<(5*128*512 + 255)/256, 256>>>(pc_W1, pre_W, pc_b1, pre_b);
    pack_we_kernel<<<(5*1152*128 + 255)/256, 256>>>(post_W);

    // input transforms
    gemm2_kernel<true,128><<<dim3(NN/128, 1), 256>>>(node_feat, 64, node_feat, 64, 64,
                                                     in_W, 128, in_b, hA, 128, 64);
    gemm2_kernel<true,128><<<dim3(EB/128, 1), 256>>>(edge_feat, 16, edge_feat, 16, 16,
                                                     ein_W, 128, ein_b, ef, 128, 16);

    float* cur = hA;
    float* nxt = hB;
    for (int l = 0; l < 5; l++) {
        // X = h @ [W1a | W1b | P1 | P2] + [0 | b1 | 0 | preb]
        gemm2_kernel<false,128><<<dim3(NN/128, 4), 256>>>(cur, 128, cur, 128, 128,
                                                          Wx + l*65536, 512, bx + l*512, X, 512, 128);
        // C = ef @ P3
        gemm2_kernel<false,128><<<dim3(EB/128, 1), 256>>>(ef, 128, ef, 128, 128,
                                                          pre_W + (size_t)l*49152 + 256*128, 128,
                                                          nullptr, C, 128, 128);
        bond_kernel<<<NN*128/256, 256>>>(bond_src);
        comp_kernel<<<EC/64, 256>>>(comp_src, pc_W2 + (size_t)l*16384, pc_b2 + l*128,
                                    se_W + l*128, se_b + l);
        // h_next = [h | agg] @ W_eff + post_b   (residual + scalers folded into W_eff)
        gemm2_kernel<false,64><<<dim3(NN/64, 1), 256>>>(cur, 128, agg, 1024, 128,
                                                        We + l*147456, 128, post_b + l*128,
                                                        nxt, 128, 1152);
        float* tmp = cur; cur = nxt; nxt = tmp;
    }

    // node-wise output MLP
    gemm2_kernel<true,64 ><<<dim3(NN/64, 1), 256>>>(cur, 128, cur, 128, 128,
                                                    outn_W1, 128, outn_b1, t1, 128, 128);
    gemm2_kernel<false,64><<<dim3(NN/64, 1), 256>>>(t1, 128, t1, 128, 128,
                                                    outn_W2, 128, outn_b2, nxt, 128, 128);
    // readout
    readout_kernel<<<GG, 128>>>(nxt, ro_W1, ro_b1, ro_W2, ro_b2, (float*)d_out);
}

// round 5
// speedup vs baseline: 1.5636x; 1.5636x over previous
#include <cuda_runtime.h>
#include <cuda_bf16.h>
#include <cstdint>
#include <math.h>

#define NN 12800
#define GG 128
#define EB 51200
#define EC 204800

__device__ __forceinline__ uint32_t smem_to_u32(const void* p) {
    uint32_t a;
    asm("{ .reg .u64 t; cvta.to.shared.u64 t, %1; cvt.u32.u64 %0, t; }" : "=r"(a) : "l"(p));
    return a;
}
#define LDSM_X4(r0,r1,r2,r3, addr) \
    asm volatile("ldmatrix.sync.aligned.m8n8.x4.shared.b16 {%0,%1,%2,%3}, [%4];" \
        : "=r"(r0),"=r"(r1),"=r"(r2),"=r"(r3) : "r"(addr))
#define LDSM_X4_T(r0,r1,r2,r3, addr) \
    asm volatile("ldmatrix.sync.aligned.m8n8.x4.trans.shared.b16 {%0,%1,%2,%3}, [%4];" \
        : "=r"(r0),"=r"(r1),"=r"(r2),"=r"(r3) : "r"(addr))
#define MMA_BF16(d, a0,a1,a2,a3, b0,b1) \
    asm volatile("mma.sync.aligned.m16n8k16.row.col.f32.bf16.bf16.f32 " \
        "{%0,%1,%2,%3}, {%4,%5,%6,%7}, {%8,%9}, {%0,%1,%2,%3};" \
        : "+f"((d)[0]),"+f"((d)[1]),"+f"((d)[2]),"+f"((d)[3]) \
        : "r"(a0),"r"(a1),"r"(a2),"r"(a3), "r"(b0),"r"(b1))

// ---------------- scratch (no allocations allowed) ----------------
__device__ float g_hA[NN*128];
__device__ float g_hB[NN*128];
__device__ float g_ef[EB*128];
__device__ float g_X[NN*512];      // [A1 | A2+b1 | B1 | B2+preb] per node
__device__ float g_C[EB*128];      // ef @ P3 per layer
__device__ float g_agg[NN*1024];   // [bond agg(512) | comp agg(512)]
__device__ float g_t1[NN*128];
__device__ float g_Wx[5*128*512];
__device__ float g_bx[5*512];
__device__ float g_We[5*1152*128];
__device__ __align__(16) unsigned char g_Bimg[5*65536];  // per layer: W2 bf16 hi[128][128] + lo[128][128]

// ---------------- weight packing ----------------
__global__ void pack_wx_kernel(const float* __restrict__ pcW1, const float* __restrict__ preW,
                               const float* __restrict__ pcB1, const float* __restrict__ preB) {
    int idx = blockIdx.x * 256 + threadIdx.x;
    if (idx < 5*128*512) {
        int l = idx >> 16;
        int rem = idx & 65535;
        int k = rem >> 9;
        int c = rem & 511;
        float v;
        if (c < 128)      v = pcW1[l*32768 + k*128 + c];
        else if (c < 256) v = pcW1[l*32768 + (128+k)*128 + (c-128)];
        else if (c < 384) v = preW[l*49152 + k*128 + (c-256)];
        else              v = preW[l*49152 + (128+k)*128 + (c-384)];
        g_Wx[idx] = v;
    }
    if (idx < 5*512) {
        int l = idx >> 9, c = idx & 511;
        float v = 0.f;
        if (c >= 128 && c < 256) v = pcB1[l*128 + (c-128)];
        else if (c >= 384)       v = preB[l*128 + (c-384)];
        g_bx[idx] = v;
    }
}

__global__ void pack_we_kernel(const float* __restrict__ postW) {
    int idx = blockIdx.x * 256 + threadIdx.x;
    if (idx >= 5*1152*128) return;
    int l = idx / 147456;
    int rem = idx - l*147456;
    int r = rem >> 7, j = rem & 127;
    const float* Wl = postW + (size_t)l*409600;
    float log5  = logf(5.f);
    float log17 = logf(17.f);
    float v;
    if (r < 128) {
        v = Wl[r*128 + j] + ((r == j) ? 1.f : 0.f);   // residual folded in
    } else if (r < 640) {
        int rp = r - 128;
        v = Wl[(128+rp)*128+j] + log5*Wl[(640+rp)*128+j] + Wl[(1152+rp)*128+j]*(1.f/log5);
    } else {
        int rp = r - 640;
        v = Wl[(1664+rp)*128+j] + log17*Wl[(2176+rp)*128+j] + Wl[(2688+rp)*128+j]*(1.f/log17);
    }
    g_We[idx] = v;
}

// pack W2 ([k][j] row-major, the MMA B operand) into bf16 hi/lo images (plain layout)
__global__ void pack_bimg_kernel(const float* __restrict__ pcW2) {
    int idx = blockIdx.x * 256 + threadIdx.x;
    if (idx >= 5*16384) return;
    int l = idx >> 14;
    int rem = idx & 16383;
    float v = pcW2[l*16384 + rem];
    __nv_bfloat16 h = __float2bfloat16(v);
    __nv_bfloat16 lo = __float2bfloat16(v - __bfloat162float(h));
    unsigned char* base = g_Bimg + (size_t)l*65536;
    *(__nv_bfloat16*)(base + rem*2)         = h;
    *(__nv_bfloat16*)(base + 32768 + rem*2) = lo;
}

// ---------------- scalar tiled GEMM (round-1, known good) ----------------
template<bool RELU>
__global__ __launch_bounds__(256) void gemm_kernel(
    const float* __restrict__ A0, int lda0,
    const float* __restrict__ A1, int lda1, int Ksplit,
    const float* __restrict__ W, int ldw,
    const float* __restrict__ bias,
    float* __restrict__ out, int ldo, int K)
{
    __shared__ float As[16][64];   // k-major
    __shared__ float Bs[16][128];
    const int t  = threadIdx.x;
    const int m0 = blockIdx.x * 64;
    const int n0 = blockIdx.y * 128;
    const int tc = t & 31, tr = t >> 5;
    const int ar = t >> 2;
    const int akq = (t & 3) << 2;

    float acc[8][4];
#pragma unroll
    for (int i = 0; i < 8; i++)
#pragma unroll
        for (int c = 0; c < 4; c++) acc[i][c] = 0.f;

    for (int k0 = 0; k0 < K; k0 += 16) {
        int kg = k0 + akq;
        const float* ap = (kg < Ksplit)
            ? (A0 + (size_t)(m0 + ar) * lda0 + kg)
            : (A1 + (size_t)(m0 + ar) * lda1 + (kg - Ksplit));
        float4 av = *(const float4*)ap;
        As[akq+0][ar] = av.x; As[akq+1][ar] = av.y;
        As[akq+2][ar] = av.z; As[akq+3][ar] = av.w;
#pragma unroll
        for (int i = 0; i < 2; i++) {
            int off = t*8 + i*4;
            int kk = off >> 7, j = off & 127;
            *(float4*)&Bs[kk][j] = *(const float4*)&W[(size_t)(k0+kk)*ldw + n0 + j];
        }
        __syncthreads();
#pragma unroll
        for (int kk = 0; kk < 16; kk++) {
            float a[8];
            *(float4*)&a[0] = *(const float4*)&As[kk][tr*8];
            *(float4*)&a[4] = *(const float4*)&As[kk][tr*8+4];
            float4 b = *(const float4*)&Bs[kk][tc*4];
#pragma unroll
            for (int i = 0; i < 8; i++) {
                acc[i][0] += a[i]*b.x; acc[i][1] += a[i]*b.y;
                acc[i][2] += a[i]*b.z; acc[i][3] += a[i]*b.w;
            }
        }
        __syncthreads();
    }
    float bv[4] = {0.f, 0.f, 0.f, 0.f};
    if (bias) {
        float4 b4 = *(const float4*)&bias[n0 + tc*4];
        bv[0]=b4.x; bv[1]=b4.y; bv[2]=b4.z; bv[3]=b4.w;
    }
#pragma unroll
    for (int i = 0; i < 8; i++) {
        float4 o;
        float* po = (float*)&o;
#pragma unroll
        for (int c = 0; c < 4; c++) {
            float v = acc[i][c] + bv[c];
            po[c] = RELU ? fmaxf(v, 0.f) : v;
        }
        *(float4*)&out[(size_t)(m0 + tr*8 + i)*ldo + n0 + tc*4] = o;
    }
}

// ---------------- fused comp-edge kernel: mma.sync bf16 3-pass ----------------
// Per 128-edge tile: a = relu(X[src,0:128] + X[dst,128:256]) -> bf16 hi/lo smem;
// m = a @ W2 + b2 via mma.sync (fp32 acc, hiA*hiB + loA*hiB + hiA*loB);
// gate = sigmoid(m . seW + seb); ec = m*gate; PNA stats over 16-edge node groups.
#define CS_MS    0                    // 128 x 132 f32 = 67584
#define CS_GS    67584                // 512
#define CS_B2    68096                // 512
#define CS_SEW   68608                // 512
#define CS_AH    69120                // 128 x 136 bf16 = 34816
#define CS_AL    103936
#define CS_BH    138752
#define CS_BL    173568
#define CS_TOTAL 208384

__global__ __launch_bounds__(256, 1) void comp_kernel(
    const int* __restrict__ src,
    int layer,
    const float* __restrict__ b2,
    const float* __restrict__ seW,
    const float* __restrict__ seB)
{
    extern __shared__ __align__(16) char smem[];
    const uint32_t sb = smem_to_u32(smem);
    const int t = threadIdx.x;
    const int w = t >> 5, lid = t & 31;
    const int e0 = blockIdx.x * 128;

    float* sM  = (float*)(smem + CS_MS);
    float* sG  = (float*)(smem + CS_GS);
    float* sb2 = (float*)(smem + CS_B2);
    float* ssw = (float*)(smem + CS_SEW);

    if (t < 128) {
        sb2[t] = b2[t];
        ssw[t] = seW[t];
    }

    // copy B images (W2 hi/lo, [k][128] bf16) into padded smem [k][136]
    {
        int row = t >> 1, half = t & 1;
        const uint4* srcH = (const uint4*)(g_Bimg + (size_t)layer*65536 + row*256 + half*128);
        const uint4* srcL = (const uint4*)(g_Bimg + (size_t)layer*65536 + 32768 + row*256 + half*128);
        uint4* dstH = (uint4*)(smem + CS_BH + row*272 + half*128);
        uint4* dstL = (uint4*)(smem + CS_BL + row*272 + half*128);
#pragma unroll
        for (int i = 0; i < 8; i++) { dstH[i] = srcH[i]; dstL[i] = srcL[i]; }
    }

    // build A tile: gather + add + relu, bf16 hi/lo, row-major padded
    {
        int row = t >> 1, half = t & 1;
        int s = src[e0 + row];
        int node = (e0 >> 4) + (row >> 4);
        const float* x1 = g_X + (size_t)s*512 + half*64;
        const float* x2 = g_X + (size_t)node*512 + 128 + half*64;
        uint32_t* ah = (uint32_t*)(smem + CS_AH + row*272 + half*128);
        uint32_t* al = (uint32_t*)(smem + CS_AL + row*272 + half*128);
#pragma unroll
        for (int i = 0; i < 64; i += 4) {
            float4 a = *(const float4*)(x1 + i);
            float4 b = *(const float4*)(x2 + i);
            float v0 = fmaxf(a.x + b.x, 0.f), v1 = fmaxf(a.y + b.y, 0.f);
            float v2 = fmaxf(a.z + b.z, 0.f), v3 = fmaxf(a.w + b.w, 0.f);
            __nv_bfloat16 h0 = __float2bfloat16(v0), h1 = __float2bfloat16(v1);
            __nv_bfloat16 h2 = __float2bfloat16(v2), h3 = __float2bfloat16(v3);
            __nv_bfloat16 l0 = __float2bfloat16(v0 - __bfloat162float(h0));
            __nv_bfloat16 l1 = __float2bfloat16(v1 - __bfloat162float(h1));
            __nv_bfloat16 l2 = __float2bfloat16(v2 - __bfloat162float(h2));
            __nv_bfloat16 l3 = __float2bfloat16(v3 - __bfloat162float(h3));
            ah[i/2]   = ((uint32_t)__bfloat16_as_ushort(h1) << 16) | __bfloat16_as_ushort(h0);
            ah[i/2+1] = ((uint32_t)__bfloat16_as_ushort(h3) << 16) | __bfloat16_as_ushort(h2);
            al[i/2]   = ((uint32_t)__bfloat16_as_ushort(l1) << 16) | __bfloat16_as_ushort(l0);
            al[i/2+1] = ((uint32_t)__bfloat16_as_ushort(l3) << 16) | __bfloat16_as_ushort(l2);
        }
    }
    __syncthreads();

    // ---- mainloop: warp w computes rows [16w, 16w+16) x 128 cols ----
    float acc[16][4];
#pragma unroll
    for (int nt = 0; nt < 16; nt++)
#pragma unroll
        for (int r = 0; r < 4; r++) acc[nt][r] = 0.f;

    // A ldmatrix address: lanes 0-7 rows 0-7 col k0; 8-15 rows 8-15; 16-23 rows 0-7 col k0+8; 24-31 rows 8-15 col k0+8
    uint32_t a_addr = sb + CS_AH + (uint32_t)((16*w + (lid & 15)) * 136 + (lid >> 4) * 8) * 2;
    // B ldmatrix.trans address: row k = (lid&7) + ((lid>>3)&1)*8, col j0 + (lid>>4)*8
    uint32_t b_addr = sb + CS_BH + (uint32_t)(((lid & 7) + ((lid >> 3) & 1) * 8) * 136 + (lid >> 4) * 8) * 2;

    for (int ks = 0; ks < 8; ks++) {
        uint32_t aH0,aH1,aH2,aH3, aL0,aL1,aL2,aL3;
        uint32_t aoff = a_addr + ks*32;
        LDSM_X4(aH0,aH1,aH2,aH3, aoff);
        LDSM_X4(aL0,aL1,aL2,aL3, aoff + (CS_AL - CS_AH));
#pragma unroll
        for (int jg = 0; jg < 4; jg++) {
            uint32_t bofs = b_addr + ks*4352 + jg*64;
            uint32_t bh0,bh1,bh2,bh3, bh4,bh5,bh6,bh7;
            uint32_t bl0,bl1,bl2,bl3, bl4,bl5,bl6,bl7;
            LDSM_X4_T(bh0,bh1,bh2,bh3, bofs);
            LDSM_X4_T(bh4,bh5,bh6,bh7, bofs + 32);
            LDSM_X4_T(bl0,bl1,bl2,bl3, bofs + (CS_BL - CS_BH));
            LDSM_X4_T(bl4,bl5,bl6,bl7, bofs + (CS_BL - CS_BH) + 32);
            MMA_BF16(acc[4*jg+0], aH0,aH1,aH2,aH3, bh0,bh1);
            MMA_BF16(acc[4*jg+0], aL0,aL1,aL2,aL3, bh0,bh1);
            MMA_BF16(acc[4*jg+0], aH0,aH1,aH2,aH3, bl0,bl1);
            MMA_BF16(acc[4*jg+1], aH0,aH1,aH2,aH3, bh2,bh3);
            MMA_BF16(acc[4*jg+1], aL0,aL1,aL2,aL3, bh2,bh3);
            MMA_BF16(acc[4*jg+1], aH0,aH1,aH2,aH3, bl2,bl3);
            MMA_BF16(acc[4*jg+2], aH0,aH1,aH2,aH3, bh4,bh5);
            MMA_BF16(acc[4*jg+2], aL0,aL1,aL2,aL3, bh4,bh5);
            MMA_BF16(acc[4*jg+2], aH0,aH1,aH2,aH3, bl4,bl5);
            MMA_BF16(acc[4*jg+3], aH0,aH1,aH2,aH3, bh6,bh7);
            MMA_BF16(acc[4*jg+3], aL0,aL1,aL2,aL3, bh6,bh7);
            MMA_BF16(acc[4*jg+3], aH0,aH1,aH2,aH3, bl6,bl7);
        }
    }

    // ---- epilogue: bias + gate partials + stage to sM ----
    {
        int r0 = 16*w + (lid >> 2);
        int r1 = r0 + 8;
        int cb = 2*(lid & 3);
        float p0 = 0.f, p1 = 0.f;
#pragma unroll
        for (int nt = 0; nt < 16; nt++) {
            int c0 = 8*nt + cb;
            float bb0 = sb2[c0], bb1 = sb2[c0+1];
            float w0 = ssw[c0], w1 = ssw[c0+1];
            float m0 = acc[nt][0] + bb0, m1 = acc[nt][1] + bb1;
            float m2 = acc[nt][2] + bb0, m3 = acc[nt][3] + bb1;
            p0 += m0*w0 + m1*w1;
            p1 += m2*w0 + m3*w1;
            sM[r0*132 + c0]     = m0;
            sM[r0*132 + c0 + 1] = m1;
            sM[r1*132 + c0]     = m2;
            sM[r1*132 + c0 + 1] = m3;
        }
        p0 += __shfl_xor_sync(0xffffffffu, p0, 1);
        p0 += __shfl_xor_sync(0xffffffffu, p0, 2);
        p1 += __shfl_xor_sync(0xffffffffu, p1, 1);
        p1 += __shfl_xor_sync(0xffffffffu, p1, 2);
        if ((lid & 3) == 0) {
            float sbv = seB[0];
            sG[r0] = 1.f / (1.f + expf(-(p0 + sbv)));
            sG[r1] = 1.f / (1.f + expf(-(p1 + sbv)));
        }
    }
    __syncthreads();

    // ---- PNA stats: 8 nodes x 128 cols ----
#pragma unroll
    for (int q = 0; q < 4; q++) {
        int item = q*256 + t;
        int n8 = item >> 7, col = item & 127;
        float s = 0.f, sq = 0.f, mx = -INFINITY, mn = INFINITY;
#pragma unroll
        for (int i = 0; i < 16; i++) {
            int row = n8*16 + i;
            float v = sM[row*132 + col] * sG[row];
            s += v; sq += v*v; mx = fmaxf(mx, v); mn = fminf(mn, v);
        }
        int node = (e0 >> 4) + n8;
        float mean = s * 0.0625f;
        float sd = sqrtf(fmaxf(sq*0.0625f - mean*mean, 0.f) + 1e-5f);
        float* o = g_agg + (size_t)node*1024 + 512 + col;
        o[0]   = mean;
        o[128] = mx;
        o[256] = mn;
        o[384] = sd;
    }
}

// ---------------- bond-edge PNA (gather-add only, no GEMM) ----------------
__global__ __launch_bounds__(256) void bond_kernel(const int* __restrict__ src) {
    int idx = blockIdx.x*256 + threadIdx.x;   // NN*128 total
    int n = idx >> 7, j = idx & 127;
    float base = g_X[(size_t)n*512 + 384 + j];
    float s=0.f, q=0.f, mx=-INFINITY, mn=INFINITY;
#pragma unroll
    for (int e = 0; e < 4; e++) {
        int ei = n*4 + e;
        int sv = src[ei];
        float v = g_X[(size_t)sv*512 + 256 + j] + base + g_C[(size_t)ei*128 + j];
        s += v; q += v*v; mx = fmaxf(mx, v); mn = fminf(mn, v);
    }
    float mean = s*0.25f;
    float sd = sqrtf(fmaxf(q*0.25f - mean*mean, 0.f) + 1e-5f);
    float* o = g_agg + (size_t)n*1024 + j;
    o[0] = mean; o[128] = mx; o[256] = mn; o[384] = sd;
}

// ---------------- readout: per-graph sum/mean/max + 2-layer MLP ----------------
__global__ __launch_bounds__(128) void readout_kernel(
    const float* __restrict__ h3,
    const float* __restrict__ W1, const float* __restrict__ b1,
    const float* __restrict__ W2, const float* __restrict__ b2,
    float* __restrict__ out)
{
    __shared__ float r[384];
    __shared__ float tb[128];
    int g = blockIdx.x, j = threadIdx.x;
    const float* p = h3 + (size_t)g*100*128 + j;
    float s = 0.f, mx = -INFINITY;
    for (int i = 0; i < 100; i++) {
        float v = p[i*128];
        s += v; mx = fmaxf(mx, v);
    }
    r[j] = s; r[128+j] = s/100.f; r[256+j] = mx;
    __syncthreads();
    float a = b1[j];
    for (int k = 0; k < 384; k++) a += r[k]*W1[k*128 + j];
    tb[j] = fmaxf(a, 0.f);
    __syncthreads();
    if (j < 32) {
        float o = b2[j];
        for (int k = 0; k < 128; k++) o += tb[k]*W2[k*32 + j];
        out[g*32 + j] = o;
    }
}

// ---------------- launcher ----------------
extern "C" void kernel_launch(void* const* d_in, const int* in_sizes, int n_in,
                              void* d_out, int out_size) {
    const float* node_feat = (const float*)d_in[0];
    const float* edge_feat = (const float*)d_in[1];
    const int*   bond_src  = (const int*)d_in[2];
    const int*   comp_src  = (const int*)d_in[4];
    const float* in_W   = (const float*)d_in[7];
    const float* in_b   = (const float*)d_in[8];
    const float* ein_W  = (const float*)d_in[9];
    const float* ein_b  = (const float*)d_in[10];
    const float* pre_W  = (const float*)d_in[11];
    const float* pre_b  = (const float*)d_in[12];
    const float* pc_W1  = (const float*)d_in[13];
    const float* pc_b1  = (const float*)d_in[14];
    const float* pc_W2  = (const float*)d_in[15];
    const float* pc_b2  = (const float*)d_in[16];
    const float* se_W   = (const float*)d_in[17];
    const float* se_b   = (const float*)d_in[18];
    const float* post_W = (const float*)d_in[19];
    const float* post_b = (const float*)d_in[20];
    const float* outn_W1 = (const float*)d_in[21];
    const float* outn_b1 = (const float*)d_in[22];
    const float* outn_W2 = (const float*)d_in[23];
    const float* outn_b2 = (const float*)d_in[24];
    const float* ro_W1 = (const float*)d_in[25];
    const float* ro_b1 = (const float*)d_in[26];
    const float* ro_W2 = (const float*)d_in[27];
    const float* ro_b2 = (const float*)d_in[28];

    float *hA, *hB, *ef, *X, *C, *agg, *t1, *Wx, *bx, *We;
    cudaGetSymbolAddress((void**)&hA, g_hA);
    cudaGetSymbolAddress((void**)&hB, g_hB);
    cudaGetSymbolAddress((void**)&ef, g_ef);
    cudaGetSymbolAddress((void**)&X,  g_X);
    cudaGetSymbolAddress((void**)&C,  g_C);
    cudaGetSymbolAddress((void**)&agg, g_agg);
    cudaGetSymbolAddress((void**)&t1, g_t1);
    cudaGetSymbolAddress((void**)&Wx, g_Wx);
    cudaGetSymbolAddress((void**)&bx, g_bx);
    cudaGetSymbolAddress((void**)&We, g_We);

    cudaFuncSetAttribute(comp_kernel, cudaFuncAttributeMaxDynamicSharedMemorySize, CS_TOTAL);

    pack_wx_kernel<<<(5*128*512 + 255)/256, 256>>>(pc_W1, pre_W, pc_b1, pre_b);
    pack_we_kernel<<<(5*1152*128 + 255)/256, 256>>>(post_W);
    pack_bimg_kernel<<<(5*16384 + 255)/256, 256>>>(pc_W2);

    // input transforms
    gemm_kernel<true><<<dim3(NN/64, 1), 256>>>(node_feat, 64, node_feat, 64, 64,
                                               in_W, 128, in_b, hA, 128, 64);
    gemm_kernel<true><<<dim3(EB/64, 1), 256>>>(edge_feat, 16, edge_feat, 16, 16,
                                               ein_W, 128, ein_b, ef, 128, 16);

    float* cur = hA;
    float* nxt = hB;
    for (int l = 0; l < 5; l++) {
        // X = h @ [W1a | W1b | P1 | P2] + [0 | b1 | 0 | preb]
        gemm_kernel<false><<<dim3(NN/64, 4), 256>>>(cur, 128, cur, 128, 128,
                                                    Wx + l*65536, 512, bx + l*512, X, 512, 128);
        // C = ef @ P3
        gemm_kernel<false><<<dim3(EB/64, 1), 256>>>(ef, 128, ef, 128, 128,
                                                    pre_W + (size_t)l*49152 + 256*128, 128,
                                                    nullptr, C, 128, 128);
        bond_kernel<<<NN*128/256, 256>>>(bond_src);
        comp_kernel<<<EC/128, 256, CS_TOTAL>>>(comp_src, l, pc_b2 + l*128,
                                               se_W + l*128, se_b + l);
        // h_next = [h | agg] @ W_eff + post_b   (residual + scalers folded into W_eff)
        gemm_kernel<false><<<dim3(NN/64, 1), 256>>>(cur, 128, agg, 1024, 128,
                                                    We + l*147456, 128, post_b + l*128,
                                                    nxt, 128, 1152);
        float* tmp = cur; cur = nxt; nxt = tmp;
    }

    // node-wise output MLP
    gemm_kernel<true ><<<dim3(NN/64, 1), 256>>>(cur, 128, cur, 128, 128,
                                                outn_W1, 128, outn_b1, t1, 128, 128);
    gemm_kernel<false><<<dim3(NN/64, 1), 256>>>(t1, 128, t1, 128, 128,
                                                outn_W2, 128, outn_b2, nxt, 128, 128);
    // readout
    readout_kernel<<<GG, 128>>>(nxt, ro_W1, ro_b1, ro_W2, ro_b2, (float*)d_out);
}

// round 6
// speedup vs baseline: 2.0795x; 1.3299x over previous
#include <cuda_runtime.h>
#include <cuda_bf16.h>
#include <cstdint>
#include <math.h>

#define NN 12800
#define GG 128
#define EB 51200
#define EC 204800

__device__ __forceinline__ uint32_t smem_to_u32(const void* p) {
    uint32_t a;
    asm("{ .reg .u64 t; cvta.to.shared.u64 t, %1; cvt.u32.u64 %0, t; }" : "=r"(a) : "l"(p));
    return a;
}
#define LDSM_X4(r0,r1,r2,r3, addr) \
    asm volatile("ldmatrix.sync.aligned.m8n8.x4.shared.b16 {%0,%1,%2,%3}, [%4];" \
        : "=r"(r0),"=r"(r1),"=r"(r2),"=r"(r3) : "r"(addr))
#define LDSM_X4_T(r0,r1,r2,r3, addr) \
    asm volatile("ldmatrix.sync.aligned.m8n8.x4.trans.shared.b16 {%0,%1,%2,%3}, [%4];" \
        : "=r"(r0),"=r"(r1),"=r"(r2),"=r"(r3) : "r"(addr))
#define MMA_BF16(d, a0,a1,a2,a3, b0,b1) \
    asm volatile("mma.sync.aligned.m16n8k16.row.col.f32.bf16.bf16.f32 " \
        "{%0,%1,%2,%3}, {%4,%5,%6,%7}, {%8,%9}, {%0,%1,%2,%3};" \
        : "+f"((d)[0]),"+f"((d)[1]),"+f"((d)[2]),"+f"((d)[3]) \
        : "r"(a0),"r"(a1),"r"(a2),"r"(a3), "r"(b0),"r"(b1))

// ---------------- scratch (no allocations allowed) ----------------
__device__ float g_hA[NN*128];
__device__ float g_hB[NN*128];
__device__ float g_ef[EB*128];
__device__ float g_X[NN*512];      // [A1 | A2+b1 | B1 | B2+preb] per node
__device__ float g_C[EB*128];      // ef @ P3 per layer
__device__ float g_agg[NN*1024];   // [bond agg(512) | comp agg(512)]
__device__ float g_t1[NN*128];
__device__ float g_Wx[5*128*512];
__device__ float g_bx[5*512];
__device__ float g_We[5*1152*128];
__device__ __align__(16) unsigned char g_Bimg[5*65536];       // W2 bf16 hi+lo per layer (comp kernel)
__device__ __align__(16) __nv_bfloat16 g_WxI[2*5*65536];      // hi[5][128][512] then lo
__device__ __align__(16) __nv_bfloat16 g_P3I[2*5*16384];      // hi[5][128][128] then lo
__device__ __align__(16) __nv_bfloat16 g_WeI[2*5*147456];     // hi[5][1152][128] then lo
__device__ __align__(16) __nv_bfloat16 g_OnI[4*16384];        // hiW1 | loW1 | hiW2 | loW2

// ---------------- weight packing ----------------
__global__ void pack_wx_kernel(const float* __restrict__ pcW1, const float* __restrict__ preW,
                               const float* __restrict__ pcB1, const float* __restrict__ preB) {
    int idx = blockIdx.x * 256 + threadIdx.x;
    if (idx < 5*128*512) {
        int l = idx >> 16;
        int rem = idx & 65535;
        int k = rem >> 9;
        int c = rem & 511;
        float v;
        if (c < 128)      v = pcW1[l*32768 + k*128 + c];
        else if (c < 256) v = pcW1[l*32768 + (128+k)*128 + (c-128)];
        else if (c < 384) v = preW[l*49152 + k*128 + (c-256)];
        else              v = preW[l*49152 + (128+k)*128 + (c-384)];
        g_Wx[idx] = v;
    }
    if (idx < 5*512) {
        int l = idx >> 9, c = idx & 511;
        float v = 0.f;
        if (c >= 128 && c < 256) v = pcB1[l*128 + (c-128)];
        else if (c >= 384)       v = preB[l*128 + (c-384)];
        g_bx[idx] = v;
    }
}

__global__ void pack_we_kernel(const float* __restrict__ postW) {
    int idx = blockIdx.x * 256 + threadIdx.x;
    if (idx >= 5*1152*128) return;
    int l = idx / 147456;
    int rem = idx - l*147456;
    int r = rem >> 7, j = rem & 127;
    const float* Wl = postW + (size_t)l*409600;
    float log5  = logf(5.f);
    float log17 = logf(17.f);
    float v;
    if (r < 128) {
        v = Wl[r*128 + j] + ((r == j) ? 1.f : 0.f);   // residual folded in
    } else if (r < 640) {
        int rp = r - 128;
        v = Wl[(128+rp)*128+j] + log5*Wl[(640+rp)*128+j] + Wl[(1152+rp)*128+j]*(1.f/log5);
    } else {
        int rp = r - 640;
        v = Wl[(1664+rp)*128+j] + log17*Wl[(2176+rp)*128+j] + Wl[(2688+rp)*128+j]*(1.f/log17);
    }
    g_We[idx] = v;
}

// pack W2 ([k][j] row-major, comp MMA B operand) into bf16 hi/lo images
__global__ void pack_bimg_kernel(const float* __restrict__ pcW2) {
    int idx = blockIdx.x * 256 + threadIdx.x;
    if (idx >= 5*16384) return;
    int l = idx >> 14;
    int rem = idx & 16383;
    float v = pcW2[l*16384 + rem];
    __nv_bfloat16 h = __float2bfloat16(v);
    __nv_bfloat16 lo = __float2bfloat16(v - __bfloat162float(h));
    unsigned char* base = g_Bimg + (size_t)l*65536;
    *(__nv_bfloat16*)(base + rem*2)         = h;
    *(__nv_bfloat16*)(base + 32768 + rem*2) = lo;
}

// generic fp32 -> bf16 hi/lo split: dst[0,n) hi, dst[n,2n) lo
__global__ void pack_img_kernel(const float* __restrict__ src, __nv_bfloat16* __restrict__ dst, int n) {
    int i = blockIdx.x * 256 + threadIdx.x;
    if (i >= n) return;
    float v = src[i];
    __nv_bfloat16 h = __float2bfloat16(v);
    dst[i]     = h;
    dst[n + i] = __float2bfloat16(v - __bfloat162float(h));
}

// P3 slices of pre_W -> bf16 hi/lo images
__global__ void pack_p3_kernel(const float* __restrict__ preW) {
    int idx = blockIdx.x * 256 + threadIdx.x;
    if (idx >= 5*16384) return;
    int l = idx >> 14, rem = idx & 16383;
    float v = preW[l*49152 + 32768 + rem];
    __nv_bfloat16 h = __float2bfloat16(v);
    g_P3I[idx]           = h;
    g_P3I[5*16384 + idx] = __float2bfloat16(v - __bfloat162float(h));
}

// ---------------- scalar tiled GEMM (small inputs only) ----------------
template<bool RELU>
__global__ __launch_bounds__(256) void gemm_kernel(
    const float* __restrict__ A0, int lda0,
    const float* __restrict__ A1, int lda1, int Ksplit,
    const float* __restrict__ W, int ldw,
    const float* __restrict__ bias,
    float* __restrict__ out, int ldo, int K)
{
    __shared__ float As[16][64];   // k-major
    __shared__ float Bs[16][128];
    const int t  = threadIdx.x;
    const int m0 = blockIdx.x * 64;
    const int n0 = blockIdx.y * 128;
    const int tc = t & 31, tr = t >> 5;
    const int ar = t >> 2;
    const int akq = (t & 3) << 2;

    float acc[8][4];
#pragma unroll
    for (int i = 0; i < 8; i++)
#pragma unroll
        for (int c = 0; c < 4; c++) acc[i][c] = 0.f;

    for (int k0 = 0; k0 < K; k0 += 16) {
        int kg = k0 + akq;
        const float* ap = (kg < Ksplit)
            ? (A0 + (size_t)(m0 + ar) * lda0 + kg)
            : (A1 + (size_t)(m0 + ar) * lda1 + (kg - Ksplit));
        float4 av = *(const float4*)ap;
        As[akq+0][ar] = av.x; As[akq+1][ar] = av.y;
        As[akq+2][ar] = av.z; As[akq+3][ar] = av.w;
#pragma unroll
        for (int i = 0; i < 2; i++) {
            int off = t*8 + i*4;
            int kk = off >> 7, j = off & 127;
            *(float4*)&Bs[kk][j] = *(const float4*)&W[(size_t)(k0+kk)*ldw + n0 + j];
        }
        __syncthreads();
#pragma unroll
        for (int kk = 0; kk < 16; kk++) {
            float a[8];
            *(float4*)&a[0] = *(const float4*)&As[kk][tr*8];
            *(float4*)&a[4] = *(const float4*)&As[kk][tr*8+4];
            float4 b = *(const float4*)&Bs[kk][tc*4];
#pragma unroll
            for (int i = 0; i < 8; i++) {
                acc[i][0] += a[i]*b.x; acc[i][1] += a[i]*b.y;
                acc[i][2] += a[i]*b.z; acc[i][3] += a[i]*b.w;
            }
        }
        __syncthreads();
    }
    float bv[4] = {0.f, 0.f, 0.f, 0.f};
    if (bias) {
        float4 b4 = *(const float4*)&bias[n0 + tc*4];
        bv[0]=b4.x; bv[1]=b4.y; bv[2]=b4.z; bv[3]=b4.w;
    }
#pragma unroll
    for (int i = 0; i < 8; i++) {
        float4 o;
        float* po = (float*)&o;
#pragma unroll
        for (int c = 0; c < 4; c++) {
            float v = acc[i][c] + bv[c];
            po[c] = RELU ? fmaxf(v, 0.f) : v;
        }
        *(float4*)&out[(size_t)(m0 + tr*8 + i)*ldo + n0 + tc*4] = o;
    }
}

// ---------------- generic tensor GEMM: out = act(A @ B + bias), bf16 hi/lo 3-pass ----------
// A fp32 (virtually concat A0|A1 at Ksplit, both 16-aligned splits); B pre-split bf16 images.
// Tile 128x128, K streamed in 32-chunks. 256 threads, warp w owns rows [16w,16w+16).
template<bool RELU>
__global__ __launch_bounds__(256) void tgemm_kernel(
    const float* __restrict__ A0, int lda0,
    const float* __restrict__ A1, int lda1, int Ksplit,
    const __nv_bfloat16* __restrict__ Bhi, const __nv_bfloat16* __restrict__ Blo, int ldb,
    const float* __restrict__ bias,
    float* __restrict__ out, int ldo, int K)
{
    __shared__ __align__(16) __nv_bfloat16 sAH[128*40];
    __shared__ __align__(16) __nv_bfloat16 sAL[128*40];
    __shared__ __align__(16) __nv_bfloat16 sBH[32*136];
    __shared__ __align__(16) __nv_bfloat16 sBL[32*136];
    __shared__ float sBias[128];

    const int t = threadIdx.x;
    const int w = t >> 5, lid = t & 31;
    const int m0 = blockIdx.x * 128;
    const int n0 = blockIdx.y * 128;

    if (t < 128) sBias[t] = bias ? bias[n0 + t] : 0.f;

    float acc[16][4];
#pragma unroll
    for (int nt = 0; nt < 16; nt++)
#pragma unroll
        for (int r = 0; r < 4; r++) acc[nt][r] = 0.f;

    const uint32_t a_off = (uint32_t)((16*w + (lid & 15))*40 + (lid >> 4)*8) * 2;
    const uint32_t aH_addr = smem_to_u32(sAH) + a_off;
    const uint32_t aL_addr = smem_to_u32(sAL) + a_off;
    const uint32_t b_off = (uint32_t)(((lid & 7) + ((lid >> 3) & 1)*8)*136 + (lid >> 4)*8) * 2;
    const uint32_t bH_addr = smem_to_u32(sBH) + b_off;
    const uint32_t bL_addr = smem_to_u32(sBL) + b_off;

    const int arow = t >> 1, ahalf = t & 1;

    for (int k0 = 0; k0 < K; k0 += 32) {
        {   // A chunk: 16 fp32 per thread -> bf16 hi/lo
            int kg = k0 + ahalf*16;
            const float* ap = (kg < Ksplit)
                ? A0 + (size_t)(m0 + arow)*lda0 + kg
                : A1 + (size_t)(m0 + arow)*lda1 + (kg - Ksplit);
            uint32_t* dh = (uint32_t*)&sAH[arow*40 + ahalf*16];
            uint32_t* dl = (uint32_t*)&sAL[arow*40 + ahalf*16];
#pragma unroll
            for (int i = 0; i < 16; i += 4) {
                float4 a = *(const float4*)(ap + i);
                __nv_bfloat16 h0 = __float2bfloat16(a.x), h1 = __float2bfloat16(a.y);
                __nv_bfloat16 h2 = __float2bfloat16(a.z), h3 = __float2bfloat16(a.w);
                __nv_bfloat16 l0 = __float2bfloat16(a.x - __bfloat162float(h0));
                __nv_bfloat16 l1 = __float2bfloat16(a.y - __bfloat162float(h1));
                __nv_bfloat16 l2 = __float2bfloat16(a.z - __bfloat162float(h2));
                __nv_bfloat16 l3 = __float2bfloat16(a.w - __bfloat162float(h3));
                dh[i/2]   = ((uint32_t)__bfloat16_as_ushort(h1) << 16) | __bfloat16_as_ushort(h0);
                dh[i/2+1] = ((uint32_t)__bfloat16_as_ushort(h3) << 16) | __bfloat16_as_ushort(h2);
                dl[i/2]   = ((uint32_t)__bfloat16_as_ushort(l1) << 16) | __bfloat16_as_ushort(l0);
                dl[i/2+1] = ((uint32_t)__bfloat16_as_ushort(l3) << 16) | __bfloat16_as_ushort(l2);
            }
        }
        {   // B chunk: 2+2 uint4 per thread (hi + lo)
            int kk = t >> 3;
            int u = (t & 7) * 16;   // halves within row
            const uint4* shp = (const uint4*)(Bhi + (size_t)(k0 + kk)*ldb + n0 + u);
            const uint4* slp = (const uint4*)(Blo + (size_t)(k0 + kk)*ldb + n0 + u);
            uint4* dh = (uint4*)&sBH[kk*136 + u];
            uint4* dl = (uint4*)&sBL[kk*136 + u];
            dh[0] = shp[0]; dh[1] = shp[1];
            dl[0] = slp[0]; dl[1] = slp[1];
        }
        __syncthreads();
#pragma unroll
        for (int kh = 0; kh < 2; kh++) {
            uint32_t aH0,aH1,aH2,aH3, aL0,aL1,aL2,aL3;
            LDSM_X4(aH0,aH1,aH2,aH3, aH_addr + kh*32);
            LDSM_X4(aL0,aL1,aL2,aL3, aL_addr + kh*32);
#pragma unroll
            for (int jg = 0; jg < 4; jg++) {
                uint32_t bo = kh*4352 + jg*64;
                uint32_t bh0,bh1,bh2,bh3, bh4,bh5,bh6,bh7;
                uint32_t bl0,bl1,bl2,bl3, bl4,bl5,bl6,bl7;
                LDSM_X4_T(bh0,bh1,bh2,bh3, bH_addr + bo);
                LDSM_X4_T(bh4,bh5,bh6,bh7, bH_addr + bo + 32);
                LDSM_X4_T(bl0,bl1,bl2,bl3, bL_addr + bo);
                LDSM_X4_T(bl4,bl5,bl6,bl7, bL_addr + bo + 32);
                MMA_BF16(acc[4*jg+0], aH0,aH1,aH2,aH3, bh0,bh1);
                MMA_BF16(acc[4*jg+0], aL0,aL1,aL2,aL3, bh0,bh1);
                MMA_BF16(acc[4*jg+0], aH0,aH1,aH2,aH3, bl0,bl1);
                MMA_BF16(acc[4*jg+1], aH0,aH1,aH2,aH3, bh2,bh3);
                MMA_BF16(acc[4*jg+1], aL0,aL1,aL2,aL3, bh2,bh3);
                MMA_BF16(acc[4*jg+1], aH0,aH1,aH2,aH3, bl2,bl3);
                MMA_BF16(acc[4*jg+2], aH0,aH1,aH2,aH3, bh4,bh5);
                MMA_BF16(acc[4*jg+2], aL0,aL1,aL2,aL3, bh4,bh5);
                MMA_BF16(acc[4*jg+2], aH0,aH1,aH2,aH3, bl4,bl5);
                MMA_BF16(acc[4*jg+3], aH0,aH1,aH2,aH3, bh6,bh7);
                MMA_BF16(acc[4*jg+3], aL0,aL1,aL2,aL3, bh6,bh7);
                MMA_BF16(acc[4*jg+3], aH0,aH1,aH2,aH3, bl6,bl7);
            }
        }
        __syncthreads();
    }

    // epilogue: bias + optional relu, fp32 stores
    const int r0 = 16*w + (lid >> 2), r1 = r0 + 8;
    const int cb = 2*(lid & 3);
#pragma unroll
    for (int nt = 0; nt < 16; nt++) {
        int c0 = 8*nt + cb;
        float b0 = sBias[c0], b1 = sBias[c0+1];
        float v0 = acc[nt][0] + b0, v1 = acc[nt][1] + b1;
        float v2 = acc[nt][2] + b0, v3 = acc[nt][3] + b1;
        if (RELU) {
            v0 = fmaxf(v0, 0.f); v1 = fmaxf(v1, 0.f);
            v2 = fmaxf(v2, 0.f); v3 = fmaxf(v3, 0.f);
        }
        *(float2*)&out[(size_t)(m0 + r0)*ldo + n0 + c0] = make_float2(v0, v1);
        *(float2*)&out[(size_t)(m0 + r1)*ldo + n0 + c0] = make_float2(v2, v3);
    }
}

// ---------------- fused comp-edge kernel: mma.sync bf16 3-pass (round-5, passing) ---------
#define CS_MS    0                    // 128 x 132 f32 = 67584
#define CS_GS    67584                // 512
#define CS_B2    68096                // 512
#define CS_SEW   68608                // 512
#define CS_AH    69120                // 128 x 136 bf16 = 34816
#define CS_AL    103936
#define CS_BH    138752
#define CS_BL    173568
#define CS_TOTAL 208384

__global__ __launch_bounds__(256, 1) void comp_kernel(
    const int* __restrict__ src,
    int layer,
    const float* __restrict__ b2,
    const float* __restrict__ seW,
    const float* __restrict__ seB)
{
    extern __shared__ __align__(16) char smem[];
    const uint32_t sb = smem_to_u32(smem);
    const int t = threadIdx.x;
    const int w = t >> 5, lid = t & 31;
    const int e0 = blockIdx.x * 128;

    float* sM  = (float*)(smem + CS_MS);
    float* sG  = (float*)(smem + CS_GS);
    float* sb2 = (float*)(smem + CS_B2);
    float* ssw = (float*)(smem + CS_SEW);

    if (t < 128) {
        sb2[t] = b2[t];
        ssw[t] = seW[t];
    }

    {   // copy W2 hi/lo images into padded smem [k][136]
        int row = t >> 1, half = t & 1;
        const uint4* srcH = (const uint4*)(g_Bimg + (size_t)layer*65536 + row*256 + half*128);
        const uint4* srcL = (const uint4*)(g_Bimg + (size_t)layer*65536 + 32768 + row*256 + half*128);
        uint4* dstH = (uint4*)(smem + CS_BH + row*272 + half*128);
        uint4* dstL = (uint4*)(smem + CS_BL + row*272 + half*128);
#pragma unroll
        for (int i = 0; i < 8; i++) { dstH[i] = srcH[i]; dstL[i] = srcL[i]; }
    }

    {   // build A tile: gather + add + relu, bf16 hi/lo
        int row = t >> 1, half = t & 1;
        int s = src[e0 + row];
        int node = (e0 >> 4) + (row >> 4);
        const float* x1 = g_X + (size_t)s*512 + half*64;
        const float* x2 = g_X + (size_t)node*512 + 128 + half*64;
        uint32_t* ah = (uint32_t*)(smem + CS_AH + row*272 + half*128);
        uint32_t* al = (uint32_t*)(smem + CS_AL + row*272 + half*128);
#pragma unroll
        for (int i = 0; i < 64; i += 4) {
            float4 a = *(const float4*)(x1 + i);
            float4 b = *(const float4*)(x2 + i);
            float v0 = fmaxf(a.x + b.x, 0.f), v1 = fmaxf(a.y + b.y, 0.f);
            float v2 = fmaxf(a.z + b.z, 0.f), v3 = fmaxf(a.w + b.w, 0.f);
            __nv_bfloat16 h0 = __float2bfloat16(v0), h1 = __float2bfloat16(v1);
            __nv_bfloat16 h2 = __float2bfloat16(v2), h3 = __float2bfloat16(v3);
            __nv_bfloat16 l0 = __float2bfloat16(v0 - __bfloat162float(h0));
            __nv_bfloat16 l1 = __float2bfloat16(v1 - __bfloat162float(h1));
            __nv_bfloat16 l2 = __float2bfloat16(v2 - __bfloat162float(h2));
            __nv_bfloat16 l3 = __float2bfloat16(v3 - __bfloat162float(h3));
            ah[i/2]   = ((uint32_t)__bfloat16_as_ushort(h1) << 16) | __bfloat16_as_ushort(h0);
            ah[i/2+1] = ((uint32_t)__bfloat16_as_ushort(h3) << 16) | __bfloat16_as_ushort(h2);
            al[i/2]   = ((uint32_t)__bfloat16_as_ushort(l1) << 16) | __bfloat16_as_ushort(l0);
            al[i/2+1] = ((uint32_t)__bfloat16_as_ushort(l3) << 16) | __bfloat16_as_ushort(l2);
        }
    }
    __syncthreads();

    float acc[16][4];
#pragma unroll
    for (int nt = 0; nt < 16; nt++)
#pragma unroll
        for (int r = 0; r < 4; r++) acc[nt][r] = 0.f;

    uint32_t a_addr = sb + CS_AH + (uint32_t)((16*w + (lid & 15)) * 136 + (lid >> 4) * 8) * 2;
    uint32_t b_addr = sb + CS_BH + (uint32_t)(((lid & 7) + ((lid >> 3) & 1) * 8) * 136 + (lid >> 4) * 8) * 2;

    for (int ks = 0; ks < 8; ks++) {
        uint32_t aH0,aH1,aH2,aH3, aL0,aL1,aL2,aL3;
        uint32_t aoff = a_addr + ks*32;
        LDSM_X4(aH0,aH1,aH2,aH3, aoff);
        LDSM_X4(aL0,aL1,aL2,aL3, aoff + (CS_AL - CS_AH));
#pragma unroll
        for (int jg = 0; jg < 4; jg++) {
            uint32_t bofs = b_addr + ks*4352 + jg*64;
            uint32_t bh0,bh1,bh2,bh3, bh4,bh5,bh6,bh7;
            uint32_t bl0,bl1,bl2,bl3, bl4,bl5,bl6,bl7;
            LDSM_X4_T(bh0,bh1,bh2,bh3, bofs);
            LDSM_X4_T(bh4,bh5,bh6,bh7, bofs + 32);
            LDSM_X4_T(bl0,bl1,bl2,bl3, bofs + (CS_BL - CS_BH));
            LDSM_X4_T(bl4,bl5,bl6,bl7, bofs + (CS_BL - CS_BH) + 32);
            MMA_BF16(acc[4*jg+0], aH0,aH1,aH2,aH3, bh0,bh1);
            MMA_BF16(acc[4*jg+0], aL0,aL1,aL2,aL3, bh0,bh1);
            MMA_BF16(acc[4*jg+0], aH0,aH1,aH2,aH3, bl0,bl1);
            MMA_BF16(acc[4*jg+1], aH0,aH1,aH2,aH3, bh2,bh3);
            MMA_BF16(acc[4*jg+1], aL0,aL1,aL2,aL3, bh2,bh3);
            MMA_BF16(acc[4*jg+1], aH0,aH1,aH2,aH3, bl2,bl3);
            MMA_BF16(acc[4*jg+2], aH0,aH1,aH2,aH3, bh4,bh5);
            MMA_BF16(acc[4*jg+2], aL0,aL1,aL2,aL3, bh4,bh5);
            MMA_BF16(acc[4*jg+2], aH0,aH1,aH2,aH3, bl4,bl5);
            MMA_BF16(acc[4*jg+3], aH0,aH1,aH2,aH3, bh6,bh7);
            MMA_BF16(acc[4*jg+3], aL0,aL1,aL2,aL3, bh6,bh7);
            MMA_BF16(acc[4*jg+3], aH0,aH1,aH2,aH3, bl6,bl7);
        }
    }

    {   // epilogue: bias + gate partials + stage to sM
        int r0 = 16*w + (lid >> 2);
        int r1 = r0 + 8;
        int cb = 2*(lid & 3);
        float p0 = 0.f, p1 = 0.f;
#pragma unroll
        for (int nt = 0; nt < 16; nt++) {
            int c0 = 8*nt + cb;
            float bb0 = sb2[c0], bb1 = sb2[c0+1];
            float w0 = ssw[c0], w1 = ssw[c0+1];
            float m0 = acc[nt][0] + bb0, m1 = acc[nt][1] + bb1;
            float m2 = acc[nt][2] + bb0, m3 = acc[nt][3] + bb1;
            p0 += m0*w0 + m1*w1;
            p1 += m2*w0 + m3*w1;
            sM[r0*132 + c0]     = m0;
            sM[r0*132 + c0 + 1] = m1;
            sM[r1*132 + c0]     = m2;
            sM[r1*132 + c0 + 1] = m3;
        }
        p0 += __shfl_xor_sync(0xffffffffu, p0, 1);
        p0 += __shfl_xor_sync(0xffffffffu, p0, 2);
        p1 += __shfl_xor_sync(0xffffffffu, p1, 1);
        p1 += __shfl_xor_sync(0xffffffffu, p1, 2);
        if ((lid & 3) == 0) {
            float sbv = seB[0];
            sG[r0] = 1.f / (1.f + expf(-(p0 + sbv)));
            sG[r1] = 1.f / (1.f + expf(-(p1 + sbv)));
        }
    }
    __syncthreads();

    // PNA stats: 8 nodes x 128 cols
#pragma unroll
    for (int q = 0; q < 4; q++) {
        int item = q*256 + t;
        int n8 = item >> 7, col = item & 127;
        float s = 0.f, sq = 0.f, mx = -INFINITY, mn = INFINITY;
#pragma unroll
        for (int i = 0; i < 16; i++) {
            int row = n8*16 + i;
            float v = sM[row*132 + col] * sG[row];
            s += v; sq += v*v; mx = fmaxf(mx, v); mn = fminf(mn, v);
        }
        int node = (e0 >> 4) + n8;
        float mean = s * 0.0625f;
        float sd = sqrtf(fmaxf(sq*0.0625f - mean*mean, 0.f) + 1e-5f);
        float* o = g_agg + (size_t)node*1024 + 512 + col;
        o[0]   = mean;
        o[128] = mx;
        o[256] = mn;
        o[384] = sd;
    }
}

// ---------------- bond-edge PNA (gather-add only, no GEMM) ----------------
__global__ __launch_bounds__(256) void bond_kernel(const int* __restrict__ src) {
    int idx = blockIdx.x*256 + threadIdx.x;   // NN*128 total
    int n = idx >> 7, j = idx & 127;
    float base = g_X[(size_t)n*512 + 384 + j];
    float s=0.f, q=0.f, mx=-INFINITY, mn=INFINITY;
#pragma unroll
    for (int e = 0; e < 4; e++) {
        int ei = n*4 + e;
        int sv = src[ei];
        float v = g_X[(size_t)sv*512 + 256 + j] + base + g_C[(size_t)ei*128 + j];
        s += v; q += v*v; mx = fmaxf(mx, v); mn = fminf(mn, v);
    }
    float mean = s*0.25f;
    float sd = sqrtf(fmaxf(q*0.25f - mean*mean, 0.f) + 1e-5f);
    float* o = g_agg + (size_t)n*1024 + j;
    o[0] = mean; o[128] = mx; o[256] = mn; o[384] = sd;
}

// ---------------- readout: per-graph sum/mean/max + 2-layer MLP ----------------
__global__ __launch_bounds__(128) void readout_kernel(
    const float* __restrict__ h3,
    const float* __restrict__ W1, const float* __restrict__ b1,
    const float* __restrict__ W2, const float* __restrict__ b2,
    float* __restrict__ out)
{
    __shared__ float r[384];
    __shared__ float tb[128];
    int g = blockIdx.x, j = threadIdx.x;
    const float* p = h3 + (size_t)g*100*128 + j;
    float s = 0.f, mx = -INFINITY;
    for (int i = 0; i < 100; i++) {
        float v = p[i*128];
        s += v; mx = fmaxf(mx, v);
    }
    r[j] = s; r[128+j] = s/100.f; r[256+j] = mx;
    __syncthreads();
    float a = b1[j];
    for (int k = 0; k < 384; k++) a += r[k]*W1[k*128 + j];
    tb[j] = fmaxf(a, 0.f);
    __syncthreads();
    if (j < 32) {
        float o = b2[j];
        for (int k = 0; k < 128; k++) o += tb[k]*W2[k*32 + j];
        out[g*32 + j] = o;
    }
}

// ---------------- launcher ----------------
extern "C" void kernel_launch(void* const* d_in, const int* in_sizes, int n_in,
                              void* d_out, int out_size) {
    const float* node_feat = (const float*)d_in[0];
    const float* edge_feat = (const float*)d_in[1];
    const int*   bond_src  = (const int*)d_in[2];
    const int*   comp_src  = (const int*)d_in[4];
    const float* in_W   = (const float*)d_in[7];
    const float* in_b   = (const float*)d_in[8];
    const float* ein_W  = (const float*)d_in[9];
    const float* ein_b  = (const float*)d_in[10];
    const float* pre_W  = (const float*)d_in[11];
    const float* pre_b  = (const float*)d_in[12];
    const float* pc_W1  = (const float*)d_in[13];
    const float* pc_b1  = (const float*)d_in[14];
    const float* pc_W2  = (const float*)d_in[15];
    const float* pc_b2  = (const float*)d_in[16];
    const float* se_W   = (const float*)d_in[17];
    const float* se_b   = (const float*)d_in[18];
    const float* post_W = (const float*)d_in[19];
    const float* post_b = (const float*)d_in[20];
    const float* outn_W1 = (const float*)d_in[21];
    const float* outn_b1 = (const float*)d_in[22];
    const float* outn_W2 = (const float*)d_in[23];
    const float* outn_b2 = (const float*)d_in[24];
    const float* ro_W1 = (const float*)d_in[25];
    const float* ro_b1 = (const float*)d_in[26];
    const float* ro_W2 = (const float*)d_in[27];
    const float* ro_b2 = (const float*)d_in[28];

    float *hA, *hB, *ef, *X, *C, *agg, *t1, *Wx, *bx, *We;
    __nv_bfloat16 *WxI, *P3I, *WeI, *OnI;
    cudaGetSymbolAddress((void**)&hA, g_hA);
    cudaGetSymbolAddress((void**)&hB, g_hB);
    cudaGetSymbolAddress((void**)&ef, g_ef);
    cudaGetSymbolAddress((void**)&X,  g_X);
    cudaGetSymbolAddress((void**)&C,  g_C);
    cudaGetSymbolAddress((void**)&agg, g_agg);
    cudaGetSymbolAddress((void**)&t1, g_t1);
    cudaGetSymbolAddress((void**)&Wx, g_Wx);
    cudaGetSymbolAddress((void**)&bx, g_bx);
    cudaGetSymbolAddress((void**)&We, g_We);
    cudaGetSymbolAddress((void**)&WxI, g_WxI);
    cudaGetSymbolAddress((void**)&P3I, g_P3I);
    cudaGetSymbolAddress((void**)&WeI, g_WeI);
    cudaGetSymbolAddress((void**)&OnI, g_OnI);

    cudaFuncSetAttribute(comp_kernel, cudaFuncAttributeMaxDynamicSharedMemorySize, CS_TOTAL);

    pack_wx_kernel<<<(5*128*512 + 255)/256, 256>>>(pc_W1, pre_W, pc_b1, pre_b);
    pack_we_kernel<<<(5*1152*128 + 255)/256, 256>>>(post_W);
    pack_bimg_kernel<<<(5*16384 + 255)/256, 256>>>(pc_W2);
    pack_p3_kernel<<<(5*16384 + 255)/256, 256>>>(pre_W);
    pack_img_kernel<<<(5*65536 + 255)/256, 256>>>(Wx, WxI, 5*65536);
    pack_img_kernel<<<(5*147456 + 255)/256, 256>>>(We, WeI, 5*147456);
    pack_img_kernel<<<(16384 + 255)/256, 256>>>(outn_W1, OnI, 16384);
    pack_img_kernel<<<(16384 + 255)/256, 256>>>(outn_W2, OnI + 32768, 16384);

    // input transforms (small K — scalar)
    gemm_kernel<true><<<dim3(NN/64, 1), 256>>>(node_feat, 64, node_feat, 64, 64,
                                               in_W, 128, in_b, hA, 128, 64);
    gemm_kernel<true><<<dim3(EB/64, 1), 256>>>(edge_feat, 16, edge_feat, 16, 16,
                                               ein_W, 128, ein_b, ef, 128, 16);

    float* cur = hA;
    float* nxt = hB;
    for (int l = 0; l < 5; l++) {
        // X = h @ [W1a | W1b | P1 | P2] + [0 | b1 | 0 | preb]
        tgemm_kernel<false><<<dim3(NN/128, 4), 256>>>(cur, 128, cur, 128, 128,
                                                      WxI + l*65536, WxI + 5*65536 + l*65536, 512,
                                                      bx + l*512, X, 512, 128);
        // C = ef @ P3
        tgemm_kernel<false><<<dim3(EB/128, 1), 256>>>(ef, 128, ef, 128, 128,
                                                      P3I + l*16384, P3I + 5*16384 + l*16384, 128,
                                                      nullptr, C, 128, 128);
        bond_kernel<<<NN*128/256, 256>>>(bond_src);
        comp_kernel<<<EC/128, 256, CS_TOTAL>>>(comp_src, l, pc_b2 + l*128,
                                               se_W + l*128, se_b + l);
        // h_next = [h | agg] @ W_eff + post_b   (residual + scalers folded into W_eff)
        tgemm_kernel<false><<<dim3(NN/128, 1), 256>>>(cur, 128, agg, 1024, 128,
                                                      WeI + l*147456, WeI + 5*147456 + l*147456, 128,
                                                      post_b + l*128, nxt, 128, 1152);
        float* tmp = cur; cur = nxt; nxt = tmp;
    }

    // node-wise output MLP
    tgemm_kernel<true ><<<dim3(NN/128, 1), 256>>>(cur, 128, cur, 128, 128,
                                                  OnI, OnI + 16384, 128,
                                                  outn_b1, t1, 128, 128);
    tgemm_kernel<false><<<dim3(NN/128, 1), 256>>>(t1, 128, t1, 128, 128,
                                                  OnI + 32768, OnI + 49152, 128,
                                                  outn_b2, nxt, 128, 128);
    // readout
    readout_kernel<<<GG, 128>>>(nxt, ro_W1, ro_b1, ro_W2, ro_b2, (float*)d_out);
}